// round 9
// baseline (speedup 1.0000x reference)
#include <cuda_runtime.h>

// Problem constants (fixed by the reference)
#define BATCH 16384
#define DIM   2048
#define NUMCL 1000

#define THREADS     256                   // 8 warps per block
#define ROWS_PER_W  2                     // uniform work per warp
#define NWARPS      (BATCH / ROWS_PER_W)  // 8192 warps
#define NBLOCKS     (NWARPS / 8)          // 1024 blocks

// Fused-reduction state (allocation-free rule: __device__ globals).
__device__ float        g_accum  = 0.0f;
__device__ unsigned int g_ticket = 0;

struct f8 { float a[8]; };

// 256-bit load, L2 evict_last: pin the 8 MB T_EMB working set in L2.
__device__ __forceinline__ f8 ldg256_evict_last(const float* p) {
    f8 v;
    asm volatile("ld.global.nc.L2::evict_last.v8.b32 {%0,%1,%2,%3,%4,%5,%6,%7}, [%8];"
                 : "=f"(v.a[0]), "=f"(v.a[1]), "=f"(v.a[2]), "=f"(v.a[3]),
                   "=f"(v.a[4]), "=f"(v.a[5]), "=f"(v.a[6]), "=f"(v.a[7])
                 : "l"(p));
    return v;
}

// 256-bit load, L2 evict_first: stream-once data, don't pollute L2.
__device__ __forceinline__ f8 ldg256_evict_first(const float* p) {
    f8 v;
    asm volatile("ld.global.nc.L2::evict_first.v8.b32 {%0,%1,%2,%3,%4,%5,%6,%7}, [%8];"
                 : "=f"(v.a[0]), "=f"(v.a[1]), "=f"(v.a[2]), "=f"(v.a[3]),
                   "=f"(v.a[4]), "=f"(v.a[5]), "=f"(v.a[6]), "=f"(v.a[7])
                 : "l"(p));
    return v;
}

__device__ __forceinline__ float dot4(const float4& x, const float4& y, float acc) {
    return fmaf(x.x, y.x, fmaf(x.y, y.y, fmaf(x.z, y.z, fmaf(x.w, y.w, acc))));
}

// ---------------------------------------------------------------------------
// Each warp processes exactly 2 rows (8192 uniform warp-tasks, R8 schedule).
// s and c use 256-bit loads (required for L2 eviction-priority modifiers and
// index-paired for the dot product); t stays float4 (only feeds ||t||^2).
// ---------------------------------------------------------------------------
__global__ __launch_bounds__(THREADS, 7)
void dnl_fused_kernel(const float* __restrict__ s_emb,
                      const float* __restrict__ t_emb,
                      const float* __restrict__ T_EMB,
                      const int*   __restrict__ labels,
                      float*       __restrict__ out)
{
    const int warp  = threadIdx.x >> 5;                 // 0..7
    const int lane  = threadIdx.x & 31;
    const int gwarp = blockIdx.x * 8 + warp;            // 0..8191

    float warp_loss = 0.0f;

    #pragma unroll
    for (int r = 0; r < ROWS_PER_W; ++r) {
        const int row = gwarp + r * NWARPS;             // 0..16383

        const size_t row_off = (size_t)row * DIM;
        const float*  s = s_emb + row_off;
        const float4* t = (const float4*)(t_emb + row_off);

        // labels are int32 (JAX x64-disabled downcasts the reference's int64).
        int lbl = labels[row];
        lbl = (lbl < 0) ? 0 : ((lbl >= NUMCL) ? (NUMCL - 1) : lbl);
        const float* c = T_EMB + (size_t)lbl * DIM;

        float dot = 0.f, ss = 0.f, tt = 0.f, cc = 0.f;

        // 8 iters: s/c as 32B-per-lane v8 loads (paired indices), t as 2x float4
        #pragma unroll
        for (int j = 0; j < 8; ++j) {
            const int off = (j * 32 + lane) * 8;        // float index for s/c
            const f8 sv = ldg256_evict_first(s + off);
            const f8 cv = ldg256_evict_last (c + off);
            const float4 tv0 = __ldcs(&t[(2 * j)     * 32 + lane]);
            const float4 tv1 = __ldcs(&t[(2 * j + 1) * 32 + lane]);

            #pragma unroll
            for (int k = 0; k < 8; ++k) {
                dot = fmaf(sv.a[k], cv.a[k], dot);
                ss  = fmaf(sv.a[k], sv.a[k], ss);
                cc  = fmaf(cv.a[k], cv.a[k], cc);
            }
            tt = dot4(tv0, tv0, tt);
            tt = dot4(tv1, tv1, tt);
        }

        // Warp tree-reduce the four accumulators
        #pragma unroll
        for (int off = 16; off > 0; off >>= 1) {
            dot += __shfl_xor_sync(0xFFFFFFFFu, dot, off);
            ss  += __shfl_xor_sync(0xFFFFFFFFu, ss,  off);
            tt  += __shfl_xor_sync(0xFFFFFFFFu, tt,  off);
            cc  += __shfl_xor_sync(0xFFFFFFFFu, cc,  off);
        }

        const float max_norm = fmaxf(sqrtf(ss), sqrtf(tt));
        warp_loss += 1.0f - dot / (sqrtf(cc) * max_norm);
    }

    // Block-level: 8 per-warp losses -> one sum
    __shared__ float sh_loss[8];
    if (lane == 0) sh_loss[warp] = warp_loss;
    __syncthreads();

    if (threadIdx.x == 0) {
        float bsum = sh_loss[0] + sh_loss[1] + sh_loss[2] + sh_loss[3]
                   + sh_loss[4] + sh_loss[5] + sh_loss[6] + sh_loss[7];
        atomicAdd(&g_accum, bsum);

        // Make the add visible before taking a ticket
        __threadfence();
        unsigned int rank = atomicInc(&g_ticket, NBLOCKS - 1);  // wraps to 0
        if (rank == NBLOCKS - 1) {
            float total = *(volatile float*)&g_accum;
            out[0] = total * (1.0f / (float)BATCH);   // ND_WEIGHT = 1
            g_accum = 0.0f;                           // reset for next replay
        }
    }
}

// ---------------------------------------------------------------------------
// kernel_launch: graph-capturable, allocation-free, single launch.
// Inputs (metadata order): s_emb f32[B*D], t_emb f32[B*D],
//                          T_EMB f32[NUMCL*D], labels i32[B]
// Output: f32 scalar
// ---------------------------------------------------------------------------
extern "C" void kernel_launch(void* const* d_in, const int* in_sizes, int n_in,
                              void* d_out, int out_size)
{
    const float* s_emb  = (const float*)d_in[0];
    const float* t_emb  = (const float*)d_in[1];
    const float* T_EMB  = (const float*)d_in[2];
    const int*   labels = (const int*)d_in[3];
    float* out = (float*)d_out;

    dnl_fused_kernel<<<NBLOCKS, THREADS>>>(s_emb, t_emb, T_EMB, labels, out);
}